// round 9
// baseline (speedup 1.0000x reference)
#include <cuda_runtime.h>
#include <cuda_fp16.h>
#include <math.h>
#include <stdint.h>

#define NB   128
#define LQ   32
#define LDOC 180
#define DIM  128
#define NW   8

#define NTHR  256
#define QSCALE    64.0f
#define QSCALE_IV (1.0f / 64.0f)

// dynamic SMEM byte offsets
#define OFF_D      0                     // 184*256 B fp16 doc = 47104
#define OFF_Q      47104                 // 32*256 B fp16 scaled queries
#define OFF_STAGE  55296                 // 2 x 8192 B fp32 stage ring
#define OFF_SSQ    (OFF_STAGE + 8192)    // overlay on stage buf1 (dead at ssq time)
#define OFF_INVD   71680                 // 128 floats
#define OFF_INVQ   72192                 // 32 floats
#define OFF_SMASK  72320                 // 184 floats
#define SM_BYTES   73088                 // 3 CTAs/SM
#define OFF_WMAX   OFF_Q                 // overlay after post-MMA sync

__device__ float    g_scores[NB * NW];
__device__ unsigned g_ticket = 0;

__device__ __forceinline__ uint32_t smem_u32(const void* p) {
    uint32_t a;
    asm("{ .reg .u64 t; cvta.to.shared.u64 t, %1; cvt.u32.u64 %0, t; }" : "=r"(a) : "l"(p));
    return a;
}

#define CP_ASYNC16(saddr, gptr) \
    asm volatile("cp.async.cg.shared.global [%0], [%1], 16;" :: "r"(saddr), "l"(gptr))
#define CP_COMMIT()  asm volatile("cp.async.commit_group;" ::: "memory")
#define CP_WAIT1()   asm volatile("cp.async.wait_group 1;" ::: "memory")
#define CP_WAIT0()   asm volatile("cp.async.wait_group 0;" ::: "memory")

#define LDSM4(r0, r1, r2, r3, addr) \
    asm volatile("ldmatrix.sync.aligned.m8n8.x4.shared.b16 {%0,%1,%2,%3}, [%4];" \
        : "=r"(r0), "=r"(r1), "=r"(r2), "=r"(r3) : "r"(addr))

__device__ __forceinline__ void mma_f16(float* c, const uint32_t* a, const uint32_t* b) {
    asm volatile(
        "mma.sync.aligned.m16n8k16.row.col.f32.f16.f16.f32 "
        "{%0,%1,%2,%3}, {%4,%5,%6,%7}, {%8,%9}, {%0,%1,%2,%3};"
        : "+f"(c[0]), "+f"(c[1]), "+f"(c[2]), "+f"(c[3])
        : "r"(a[0]), "r"(a[1]), "r"(a[2]), "r"(a[3]), "r"(b[0]), "r"(b[1]));
}

__device__ __forceinline__ uint2 h4(float4 v) {
    __half2 a = __floats2half2_rn(v.x, v.y);
    __half2 b = __floats2half2_rn(v.z, v.w);
    uint2 r;
    r.x = *(uint32_t*)&a; r.y = *(uint32_t*)&b;
    return r;
}

// swizzled byte offset inside a [rows][256B] fp16 tile
__device__ __forceinline__ uint32_t swz(uint32_t row, uint32_t chunk, uint32_t inner) {
    return row * 256u + ((chunk ^ (row & 7u)) << 4) + inner;
}

__global__ void __launch_bounds__(NTHR, 3) maxsim_kernel(
    const float* __restrict__ qraw, const float* __restrict__ doc,
    const int* __restrict__ mask, const float* __restrict__ labels,
    float* __restrict__ out)
{
    extern __shared__ char smc[];
    const uint32_t smb = smem_u32(smc);
    float* ssq   = (float*)(smc + OFF_SSQ);
    float* sinvd = (float*)(smc + OFF_INVD);
    float* sinvq = (float*)(smc + OFF_INVQ);
    float* smask = (float*)(smc + OFF_SMASK);

    const int tid  = threadIdx.x;
    const int lane = tid & 31;
    const int w    = tid >> 5;           // 0..7
    const int bw   = blockIdx.x;
    const int b    = bw >> 3;

    const char* gdoc = (const char*)(doc + (size_t)bw * LDOC * DIM);

    // ---- issue stages 0,1 of the cp.async doc pipeline ----
    {
        const uint32_t s0 = smb + OFF_STAGE;
        CP_ASYNC16(s0 + tid * 16,        gdoc + tid * 16);
        CP_ASYNC16(s0 + tid * 16 + 4096, gdoc + tid * 16 + 4096);
        CP_COMMIT();
        const uint32_t s1 = smb + OFF_STAGE + 8192;
        CP_ASYNC16(s1 + tid * 16,        gdoc + 8192 + tid * 16);
        CP_ASYNC16(s1 + tid * 16 + 4096, gdoc + 8192 + tid * 16 + 4096);
        CP_COMMIT();
    }

    // tail rows 176..179 prefetch (warps 0..3) — LDG in flight with pipeline
    float4 tailv = make_float4(0.f, 0.f, 0.f, 0.f);
    if (w < 4)
        tailv = ((const float4*)gdoc)[(176 + w) * 32 + lane];

    // masks -> smem (overlapped with cp.async flight)
    for (int l = tid; l < LDOC; l += NTHR)
        smask[l] = (mask[bw * LDOC + l] != 0) ? 1.0f : 0.0f;

    // ---- per-query inverse norms (overlapped with cp.async flight) ----
    {
        const float* qb = qraw + (size_t)b * LQ * DIM;
        #pragma unroll
        for (int k = 0; k < 4; k++) {
            int q = w * 4 + k;
            const float* qp = qb + q * DIM + lane;
            float a0 = qp[0], a1 = qp[32], a2 = qp[64], a3 = qp[96];
            float s = a0 * a0 + a1 * a1 + a2 * a2 + a3 * a3;
            #pragma unroll
            for (int o = 16; o; o >>= 1) s += __shfl_xor_sync(0xffffffffu, s, o);
            if (lane == 0) sinvq[q] = 1.0f / fmaxf(sqrtf(s), 1e-12f);
        }
    }

    // ---- pipeline: wait stage s, convert 16 rows, issue stage s+2 ----
    const int dq = lane;
    const int d0 = dq * 4;
    const uint32_t chunk = (uint32_t)(d0 >> 3);
    const uint32_t inner = (uint32_t)((d0 & 7) * 2);
    float s0a = 0.f, s1a = 0.f, s2a = 0.f, s3a = 0.f;

    #pragma unroll 1
    for (int s = 0; s < 11; s++) {
        if (s >= 9) { CP_WAIT0(); } else { CP_WAIT1(); }
        __syncthreads();
        // convert rows s*16 + w and s*16 + w + 8 from stage buffer (s&1)
        const char* buf = smc + OFF_STAGE + (s & 1) * 8192;
        #pragma unroll
        for (int j = 0; j < 2; j++) {
            int r = s * 16 + w + j * 8;
            float4 v = *(const float4*)(buf + (w + j * 8) * 512 + dq * 16);
            float mk = smask[r];
            v.x *= mk; v.y *= mk; v.z *= mk; v.w *= mk;
            s0a += v.x * v.x; s1a += v.y * v.y; s2a += v.z * v.z; s3a += v.w * v.w;
            *(uint2*)(smc + OFF_D + swz((uint32_t)r, chunk, inner)) = h4(v);
        }
        __syncthreads();
        if (s + 2 < 11) {
            const uint32_t sb = smb + OFF_STAGE + ((s + 2) & 1) * 8192;
            const char* gb = gdoc + (s + 2) * 8192;
            CP_ASYNC16(sb + tid * 16,        gb + tid * 16);
            CP_ASYNC16(sb + tid * 16 + 4096, gb + tid * 16 + 4096);
            CP_COMMIT();
        }
    }

    // ---- tail: rows 176..179 (warps 0..3), zeros 180..183 (warps 4..7) ----
    if (w < 4) {
        int r = 176 + w;
        float mk = smask[r];
        float4 v = tailv;
        v.x *= mk; v.y *= mk; v.z *= mk; v.w *= mk;
        s0a += v.x * v.x; s1a += v.y * v.y; s2a += v.z * v.z; s3a += v.w * v.w;
        *(uint2*)(smc + OFF_D + swz((uint32_t)r, chunk, inner)) = h4(v);
    } else {
        *(uint2*)(smc + OFF_D + swz((uint32_t)(176 + w), chunk, inner)) = make_uint2(0u, 0u);
    }
    *(float4*)&ssq[tid * 4] = make_float4(s0a, s1a, s2a, s3a);
    __syncthreads();

    // ---- per-feature doc inverse norms ----
    if (tid < DIM) {
        float s = 0.f;
        #pragma unroll
        for (int wp = 0; wp < 8; wp++) s += ssq[wp * 128 + tid];
        sinvd[tid] = 1.0f / fmaxf(sqrtf(s), 1e-12f);
    }
    __syncthreads();

    // ---- queries: scale by invq*invd*QSCALE -> fp16 SMEM ----
    {
        int q = tid >> 3;                  // 8 threads per query
        int qd0 = (tid & 7) * 16;
        const float* qp = qraw + (size_t)b * LQ * DIM + q * DIM;
        float sq = sinvq[q] * QSCALE;
        #pragma unroll
        for (int i = 0; i < 4; i++) {
            int d = qd0 + i * 4;
            float4 v = *(const float4*)(qp + d);
            v.x *= sq * sinvd[d];     v.y *= sq * sinvd[d + 1];
            v.z *= sq * sinvd[d + 2]; v.w *= sq * sinvd[d + 3];
            *(uint2*)(smc + OFF_Q + swz((uint32_t)q, (uint32_t)(d >> 3),
                                        (uint32_t)((d & 7) * 2))) = h4(v);
        }
    }
    __syncthreads();

    // ---- HMMA: warp = (N half nh) x (3 M-tiles) ----
    const int nh = w & 1;                  // queries nh*16 .. nh*16+15
    const int mt = (w >> 1) * 3;           // M tiles mt..mt+2 (tile 11 -> row 168)
    int mstart[3];
    #pragma unroll
    for (int j = 0; j < 3; j++) {
        int r = (mt + j) * 16;
        mstart[j] = (r > 168) ? 168 : r;
    }

    const uint32_t rA = (uint32_t)((lane & 7) + ((lane >> 3) & 1) * 8);
    const uint32_t cA = (uint32_t)(lane >> 4);
    const uint32_t rB = (uint32_t)((lane & 7) + (lane >> 4) * 8 + nh * 16);
    const uint32_t cB = (uint32_t)((lane >> 3) & 1);

    const uint32_t dti = smb + OFF_D;
    const uint32_t qti = smb + OFF_Q;

    float acc[3][2][4];
    #pragma unroll
    for (int m = 0; m < 3; m++)
        #pragma unroll
        for (int n = 0; n < 2; n++)
            #pragma unroll
            for (int j = 0; j < 4; j++) acc[m][n][j] = 0.f;

    #pragma unroll 4
    for (int k = 0; k < 8; k++) {
        const uint32_t kc = 2u * (uint32_t)k;
        uint32_t bh[4];
        LDSM4(bh[0], bh[1], bh[2], bh[3], qti + swz(rB, kc + cB, 0));
        #pragma unroll
        for (int m = 0; m < 3; m++) {
            uint32_t ah[4];
            LDSM4(ah[0], ah[1], ah[2], ah[3],
                  dti + swz((uint32_t)mstart[m] + rA, kc + cA, 0));
            mma_f16(acc[m][0], ah, &bh[0]);
            mma_f16(acc[m][1], ah, &bh[2]);
        }
    }
    __syncthreads();                       // Q tile dead; warpmax overlays it

    float* warpmax = (float*)(smc + OFF_WMAX);   // [8 warps][16 cols]
    #pragma unroll
    for (int n = 0; n < 2; n++) {
        #pragma unroll
        for (int j = 0; j < 2; j++) {
            float mx = fmaxf(acc[0][n][j], acc[0][n][j + 2]);
            mx = fmaxf(mx, fmaxf(acc[1][n][j], acc[1][n][j + 2]));
            mx = fmaxf(mx, fmaxf(acc[2][n][j], acc[2][n][j + 2]));
            mx = fmaxf(mx, __shfl_xor_sync(0xffffffffu, mx, 4));
            mx = fmaxf(mx, __shfl_xor_sync(0xffffffffu, mx, 8));
            mx = fmaxf(mx, __shfl_xor_sync(0xffffffffu, mx, 16));
            if (lane < 4)
                warpmax[w * 16 + n * 8 + lane * 2 + j] = mx * QSCALE_IV;
        }
    }
    __syncthreads();

    if (tid < 32) {
        int half = tid >> 4, c = tid & 15;
        float v = warpmax[(half)      * 16 + c];
        v = fmaxf(v, warpmax[(half + 2) * 16 + c]);
        v = fmaxf(v, warpmax[(half + 4) * 16 + c]);
        v = fmaxf(v, warpmax[(half + 6) * 16 + c]);
        #pragma unroll
        for (int o = 16; o; o >>= 1) v += __shfl_xor_sync(0xffffffffu, v, o);
        if (tid == 0) g_scores[bw] = v;
    }

    // ---- grid ticket: last block computes the KL loss ----
    __shared__ unsigned slast;
    if (tid == 0) {
        __threadfence();
        unsigned t = atomicAdd(&g_ticket, 1u);
        slast = (t == (unsigned)(NB * NW - 1)) ? 1u : 0u;
    }
    __syncthreads();
    if (slast) {
        if (tid == 0) g_ticket = 0;
        __threadfence();
        float accl = 0.f;
        if (tid < NB) {
            float s[NW], lab[NW];
            #pragma unroll
            for (int ww = 0; ww < NW; ww++) {
                s[ww]   = *((volatile float*)&g_scores[tid * NW + ww]);
                lab[ww] = labels[tid * NW + ww];
            }
            float m = s[0];
            #pragma unroll
            for (int ww = 1; ww < NW; ww++) m = fmaxf(m, s[ww]);
            float se = 0.f;
            #pragma unroll
            for (int ww = 0; ww < NW; ww++) se += expf(s[ww] - m);
            float lse = logf(se) + m;
            #pragma unroll
            for (int ww = 0; ww < NW; ww++)
                accl += expf(lab[ww]) * (lab[ww] - (s[ww] - lse));
        }
        #pragma unroll
        for (int o = 16; o; o >>= 1) accl += __shfl_xor_sync(0xffffffffu, accl, o);
        __shared__ float red2[8];
        if (lane == 0) red2[w] = accl;
        __syncthreads();
        if (tid == 0) {
            float t2 = 0.f;
            #pragma unroll
            for (int i = 0; i < 8; i++) t2 += red2[i];
            out[0] = t2 / (float)NB;
        }
    }
}

// ---------------- launch ----------------
extern "C" void kernel_launch(void* const* d_in, const int* in_sizes, int n_in,
                              void* d_out, int out_size) {
    const float* q      = (const float*)d_in[0];
    const float* doc    = (const float*)d_in[1];
    const int*   mask   = (const int*)d_in[2];
    const float* labels = (const float*)d_in[3];
    float* out = (float*)d_out;

    cudaFuncSetAttribute(maxsim_kernel,
                         cudaFuncAttributeMaxDynamicSharedMemorySize, SM_BYTES);

    maxsim_kernel<<<NB * NW, NTHR, SM_BYTES>>>(q, doc, mask, labels, out);
}

// round 12
// speedup vs baseline: 1.2815x; 1.2815x over previous
#include <cuda_runtime.h>
#include <cuda_fp16.h>
#include <math.h>
#include <stdint.h>

#define NB   128
#define LQ   32
#define LDOC 180
#define DIM  128
#define NW   8

#define NTHR  256
#define QSCALE    64.0f
#define QSCALE_IV (1.0f / 64.0f)

// dynamic SMEM byte offsets
#define OFF_D     0                    // 184*256 B fp16 doc = 47104
#define OFF_Q     47104                // 32*256 B fp16 scaled queries
#define OFF_SSQ   47104                // overlay: ssq consumed before Q written
#define OFF_INVD  55296                // 128 floats
#define OFF_INVQ  55808                // 32 floats
#define SM_BYTES  55936
#define OFF_WMAX  OFF_Q                // overlay after post-MMA sync

__device__ float    g_scores[NB * NW];
__device__ unsigned g_ticket = 0;

__device__ __forceinline__ uint32_t smem_u32(const void* p) {
    uint32_t a;
    asm("{ .reg .u64 t; cvta.to.shared.u64 t, %1; cvt.u32.u64 %0, t; }" : "=r"(a) : "l"(p));
    return a;
}

#define LDSM4(r0, r1, r2, r3, addr) \
    asm volatile("ldmatrix.sync.aligned.m8n8.x4.shared.b16 {%0,%1,%2,%3}, [%4];" \
        : "=r"(r0), "=r"(r1), "=r"(r2), "=r"(r3) : "r"(addr))

__device__ __forceinline__ void mma_f16(float* c, const uint32_t* a, const uint32_t* b) {
    asm volatile(
        "mma.sync.aligned.m16n8k16.row.col.f32.f16.f16.f32 "
        "{%0,%1,%2,%3}, {%4,%5,%6,%7}, {%8,%9}, {%0,%1,%2,%3};"
        : "+f"(c[0]), "+f"(c[1]), "+f"(c[2]), "+f"(c[3])
        : "r"(a[0]), "r"(a[1]), "r"(a[2]), "r"(a[3]), "r"(b[0]), "r"(b[1]));
}

__device__ __forceinline__ uint2 h4(float4 v) {
    __half2 a = __floats2half2_rn(v.x, v.y);
    __half2 b = __floats2half2_rn(v.z, v.w);
    uint2 r;
    r.x = *(uint32_t*)&a; r.y = *(uint32_t*)&b;
    return r;
}

// swizzled byte offset inside a [rows][256B] fp16 tile
__device__ __forceinline__ uint32_t swz(uint32_t row, uint32_t chunk, uint32_t inner) {
    return row * 256u + ((chunk ^ (row & 7u)) << 4) + inner;
}

__global__ void __launch_bounds__(NTHR, 3) maxsim_kernel(
    const float* __restrict__ qraw, const float* __restrict__ doc,
    const int* __restrict__ mask, const float* __restrict__ labels,
    float* __restrict__ out)
{
    extern __shared__ char smc[];
    const uint32_t smb = smem_u32(smc);
    float* ssq   = (float*)(smc + OFF_SSQ);
    float* sinvd = (float*)(smc + OFF_INVD);
    float* sinvq = (float*)(smc + OFF_INVQ);

    const int tid  = threadIdx.x;
    const int lane = tid & 31;
    const int w    = tid >> 5;           // 0..7
    const int bw   = blockIdx.x;
    const int b    = bw >> 3;

    // ---- doc stream: fp32 -> fp16 swizzled SMEM + per-feature sumsq ----
    // thread: quad column dq=lane, rows w+8i. Software-pipelined batches of 4:
    // prefetch batch g+1 while converting batch g (keeps 4 LDG.128 in flight).
    {
        const int dq = lane;
        const int d0 = dq * 4;
        const uint32_t chunk = (uint32_t)(d0 >> 3);
        const uint32_t inner = (uint32_t)((d0 & 7) * 2);
        float s0 = 0.f, s1 = 0.f, s2 = 0.f, s3 = 0.f;
        const float4* dg = (const float4*)(doc + (size_t)bw * LDOC * DIM);
        const int* mrow = mask + bw * LDOC;

        float4 vb[4]; float mk[4];
        // prefetch batch 0: i = 0..3
        #pragma unroll
        for (int j = 0; j < 4; j++) {
            int l = w + 8 * j;
            vb[j] = dg[l * 32 + dq];
            mk[j] = (mrow[l] != 0) ? 1.0f : 0.0f;
        }

        #pragma unroll
        for (int g = 0; g < 5; g++) {
            float4 nv[4]; float nm[4];
            if (g < 4) {
                // prefetch i = 4g+4 .. 4g+7
                #pragma unroll
                for (int j = 0; j < 4; j++) {
                    int l = w + 8 * (4 * g + 4 + j);
                    nv[j] = dg[l * 32 + dq];
                    nm[j] = (mrow[l] != 0) ? 1.0f : 0.0f;
                }
            } else {
                // prefetch i = 20, 21 and tail row 176+w (valid w<4)
                #pragma unroll
                for (int j = 0; j < 2; j++) {
                    int l = w + 8 * (20 + j);
                    nv[j] = dg[l * 32 + dq];
                    nm[j] = (mrow[l] != 0) ? 1.0f : 0.0f;
                }
                nv[3] = make_float4(0.f, 0.f, 0.f, 0.f); nm[3] = 0.f;
                if (w < 4) {
                    int l = 176 + w;
                    nv[2] = dg[l * 32 + dq];
                    nm[2] = (mrow[l] != 0) ? 1.0f : 0.0f;
                } else {
                    nv[2] = make_float4(0.f, 0.f, 0.f, 0.f); nm[2] = 0.f;
                }
            }
            // convert batch g: rows i = 4g .. 4g+3
            #pragma unroll
            for (int j = 0; j < 4; j++) {
                int l = w + 8 * (4 * g + j);
                float4 v = vb[j];
                float m = mk[j];
                v.x *= m; v.y *= m; v.z *= m; v.w *= m;
                s0 += v.x * v.x; s1 += v.y * v.y; s2 += v.z * v.z; s3 += v.w * v.w;
                *(uint2*)(smc + OFF_D + swz((uint32_t)l, chunk, inner)) = h4(v);
            }
            #pragma unroll
            for (int j = 0; j < 4; j++) { vb[j] = nv[j]; mk[j] = nm[j]; }
        }

        // epilogue: convert i = 20, 21 (vb[0], vb[1])
        #pragma unroll
        for (int j = 0; j < 2; j++) {
            int l = w + 8 * (20 + j);
            float4 v = vb[j];
            float m = mk[j];
            v.x *= m; v.y *= m; v.z *= m; v.w *= m;
            s0 += v.x * v.x; s1 += v.y * v.y; s2 += v.z * v.z; s3 += v.w * v.w;
            *(uint2*)(smc + OFF_D + swz((uint32_t)l, chunk, inner)) = h4(v);
        }
        // tail row 176+w (real for w<4, zeros for w>=4 at rows 180..183)
        {
            float4 v = vb[2];
            float m = mk[2];
            v.x *= m; v.y *= m; v.z *= m; v.w *= m;
            s0 += v.x * v.x; s1 += v.y * v.y; s2 += v.z * v.z; s3 += v.w * v.w;
            *(uint2*)(smc + OFF_D + swz((uint32_t)(176 + w), chunk, inner)) = h4(v);
        }
        *(float4*)&ssq[tid * 4] = make_float4(s0, s1, s2, s3);
    }

    // ---- per-query inverse norms (warp w -> queries 4w..4w+3) ----
    {
        const float* qb = qraw + (size_t)b * LQ * DIM;
        #pragma unroll
        for (int k = 0; k < 4; k++) {
            int q = w * 4 + k;
            const float* qp = qb + q * DIM + lane;
            float a0 = qp[0], a1 = qp[32], a2 = qp[64], a3 = qp[96];
            float s = a0 * a0 + a1 * a1 + a2 * a2 + a3 * a3;
            #pragma unroll
            for (int o = 16; o; o >>= 1) s += __shfl_xor_sync(0xffffffffu, s, o);
            if (lane == 0) sinvq[q] = 1.0f / fmaxf(sqrtf(s), 1e-12f);
        }
    }
    __syncthreads();

    // ---- per-feature doc inverse norms ----
    if (tid < DIM) {
        float s = 0.f;
        #pragma unroll
        for (int wp = 0; wp < 8; wp++) s += ssq[wp * 128 + tid];
        sinvd[tid] = 1.0f / fmaxf(sqrtf(s), 1e-12f);
    }
    __syncthreads();

    // ---- queries: scale by invq*invd*QSCALE -> fp16 SMEM (overwrites ssq) ----
    {
        int q = tid >> 3;                  // 8 threads per query
        int qd0 = (tid & 7) * 16;
        const float* qp = qraw + (size_t)b * LQ * DIM + q * DIM;
        float sq = sinvq[q] * QSCALE;
        #pragma unroll
        for (int i = 0; i < 4; i++) {
            int d = qd0 + i * 4;
            float4 v = *(const float4*)(qp + d);
            v.x *= sq * sinvd[d];     v.y *= sq * sinvd[d + 1];
            v.z *= sq * sinvd[d + 2]; v.w *= sq * sinvd[d + 3];
            *(uint2*)(smc + OFF_Q + swz((uint32_t)q, (uint32_t)(d >> 3),
                                        (uint32_t)((d & 7) * 2))) = h4(v);
        }
    }
    __syncthreads();

    // ---- HMMA: warp = (N half nh) x (3 M-tiles) ----
    const int nh = w & 1;                  // queries nh*16 .. nh*16+15
    const int mt = (w >> 1) * 3;           // M tiles mt..mt+2 (tile 11 -> row 168)
    int mstart[3];
    #pragma unroll
    for (int j = 0; j < 3; j++) {
        int r = (mt + j) * 16;
        mstart[j] = (r > 168) ? 168 : r;
    }

    const uint32_t rA = (uint32_t)((lane & 7) + ((lane >> 3) & 1) * 8);
    const uint32_t cA = (uint32_t)(lane >> 4);
    const uint32_t rB = (uint32_t)((lane & 7) + (lane >> 4) * 8 + nh * 16);
    const uint32_t cB = (uint32_t)((lane >> 3) & 1);

    const uint32_t dti = smb + OFF_D;
    const uint32_t qti = smb + OFF_Q;

    float acc[3][2][4];
    #pragma unroll
    for (int m = 0; m < 3; m++)
        #pragma unroll
        for (int n = 0; n < 2; n++)
            #pragma unroll
            for (int j = 0; j < 4; j++) acc[m][n][j] = 0.f;

    #pragma unroll 4
    for (int k = 0; k < 8; k++) {
        const uint32_t kc = 2u * (uint32_t)k;
        uint32_t bh[4];
        LDSM4(bh[0], bh[1], bh[2], bh[3], qti + swz(rB, kc + cB, 0));
        #pragma unroll
        for (int m = 0; m < 3; m++) {
            uint32_t ah[4];
            LDSM4(ah[0], ah[1], ah[2], ah[3],
                  dti + swz((uint32_t)mstart[m] + rA, kc + cA, 0));
            mma_f16(acc[m][0], ah, &bh[0]);
            mma_f16(acc[m][1], ah, &bh[2]);
        }
    }
    __syncthreads();                       // Q tile dead; warpmax overlays it

    float* warpmax = (float*)(smc + OFF_WMAX);   // [8 warps][16 cols]
    #pragma unroll
    for (int n = 0; n < 2; n++) {
        #pragma unroll
        for (int j = 0; j < 2; j++) {
            float mx = fmaxf(acc[0][n][j], acc[0][n][j + 2]);
            mx = fmaxf(mx, fmaxf(acc[1][n][j], acc[1][n][j + 2]));
            mx = fmaxf(mx, fmaxf(acc[2][n][j], acc[2][n][j + 2]));
            mx = fmaxf(mx, __shfl_xor_sync(0xffffffffu, mx, 4));
            mx = fmaxf(mx, __shfl_xor_sync(0xffffffffu, mx, 8));
            mx = fmaxf(mx, __shfl_xor_sync(0xffffffffu, mx, 16));
            if (lane < 4)
                warpmax[w * 16 + n * 8 + lane * 2 + j] = mx * QSCALE_IV;
        }
    }
    __syncthreads();

    if (tid < 32) {
        int half = tid >> 4, c = tid & 15;
        float v = warpmax[(half)      * 16 + c];
        v = fmaxf(v, warpmax[(half + 2) * 16 + c]);
        v = fmaxf(v, warpmax[(half + 4) * 16 + c]);
        v = fmaxf(v, warpmax[(half + 6) * 16 + c]);
        #pragma unroll
        for (int o = 16; o; o >>= 1) v += __shfl_xor_sync(0xffffffffu, v, o);
        if (tid == 0) g_scores[bw] = v;
    }

    // ---- grid ticket: last block computes the KL loss ----
    __shared__ unsigned slast;
    if (tid == 0) {
        __threadfence();
        unsigned t = atomicAdd(&g_ticket, 1u);
        slast = (t == (unsigned)(NB * NW - 1)) ? 1u : 0u;
    }
    __syncthreads();
    if (slast) {
        if (tid == 0) g_ticket = 0;
        __threadfence();
        float accl = 0.f;
        if (tid < NB) {
            float s[NW], lab[NW];
            #pragma unroll
            for (int ww = 0; ww < NW; ww++) {
                s[ww]   = *((volatile float*)&g_scores[tid * NW + ww]);
                lab[ww] = labels[tid * NW + ww];
            }
            float m = s[0];
            #pragma unroll
            for (int ww = 1; ww < NW; ww++) m = fmaxf(m, s[ww]);
            float se = 0.f;
            #pragma unroll
            for (int ww = 0; ww < NW; ww++) se += expf(s[ww] - m);
            float lse = logf(se) + m;
            #pragma unroll
            for (int ww = 0; ww < NW; ww++)
                accl += expf(lab[ww]) * (lab[ww] - (s[ww] - lse));
        }
        #pragma unroll
        for (int o = 16; o; o >>= 1) accl += __shfl_xor_sync(0xffffffffu, accl, o);
        __shared__ float red2[8];
        if (lane == 0) red2[w] = accl;
        __syncthreads();
        if (tid == 0) {
            float t2 = 0.f;
            #pragma unroll
            for (int i = 0; i < 8; i++) t2 += red2[i];
            out[0] = t2 / (float)NB;
        }
    }
}

// ---------------- launch ----------------
extern "C" void kernel_launch(void* const* d_in, const int* in_sizes, int n_in,
                              void* d_out, int out_size) {
    const float* q      = (const float*)d_in[0];
    const float* doc    = (const float*)d_in[1];
    const int*   mask   = (const int*)d_in[2];
    const float* labels = (const float*)d_in[3];
    float* out = (float*)d_out;

    cudaFuncSetAttribute(maxsim_kernel,
                         cudaFuncAttributeMaxDynamicSharedMemorySize, SM_BYTES);

    maxsim_kernel<<<NB * NW, NTHR, SM_BYTES>>>(q, doc, mask, labels, out);
}